// round 9
// baseline (speedup 1.0000x reference)
#include <cuda_runtime.h>
#include <cuda_bf16.h>

#define NB 8
#define THREADS 256   // 8 warps; warp w owns batch item b0+w

__device__ __forceinline__ float clip01(float v) { return fminf(fmaxf(v, 0.0f), 1.0f); }

__global__ __launch_bounds__(THREADS, 3)   // cap regs (~85) -> 3 CTAs/SM, 24 warps
void nnue_kernel(const int*   __restrict__ wic,  const float* __restrict__ wval,
                 const int*   __restrict__ bic,  const float* __restrict__ bval,
                 const int*   __restrict__ stm,
                 const float* __restrict__ ftw,  const float* __restrict__ ftb,
                 const float* __restrict__ fc1w, const float* __restrict__ fc1b,
                 const float* __restrict__ fc2w, const float* __restrict__ fc2b,
                 const float* __restrict__ fcow, const float* __restrict__ fcob,
                 float* __restrict__ out)
{
    __shared__ float sx[NB][512];      // concat'd + clipped FT outputs
    __shared__ float sh1[NB][32];      // fc1 outputs
    __shared__ float s_fc2[32][33];    // padded: conflict-free row access

    const int tid  = threadIdx.x;
    const int warp = tid >> 5;
    const int lane = tid & 31;
    const int b0   = blockIdx.x * NB;
    const int item = warp;             // one warp per batch item

    // fc2 weights into padded shared (coalesced 4 KB read)
    for (int i = tid; i < 32 * 32; i += THREADS)
        s_fc2[i >> 5][i & 31] = fc2w[i];

    // ---- per-lane sparse slot (k = lane); broadcast later via shfl ----
    // All four loads issued unconditionally (arrays are dense [B,K]);
    // padding handled arithmetically: -1 -> row 0, value 0 (row 0 stays L1-hot).
    const int   g   = (b0 + item) * 32 + lane;
    const int   wi  = wic[g];
    const int   bi  = bic[g];
    const float wv  = wval[g];
    const float bv  = bval[g];
    const int   myWic = wi < 0 ? 0 : wi;
    const int   myBic = bi < 0 ? 0 : bi;
    const float myWv  = wi < 0 ? 0.f : wv;
    const float myBv  = bi < 0 ? 0.f : bv;

    // ---- feature-transformer gather: warp-per-item, 2 float4/thread/row ----
    // thread covers H positions [4L..4L+3] and [128+4L..128+4L+3]
    const int h0 = lane * 4;

    float4 aW0 = make_float4(0.f,0.f,0.f,0.f), aW1 = make_float4(0.f,0.f,0.f,0.f);
    float4 aB0 = make_float4(0.f,0.f,0.f,0.f), aB1 = make_float4(0.f,0.f,0.f,0.f);

    // Straight-line body; unroll 4 keeps ~16 LDG.128 destinations alive,
    // fitting the 3-CTA register budget without spills (prev: unroll 8 -> 178 regs).
    #pragma unroll 4
    for (int k = 0; k < 32; k++) {
        const int   iw = __shfl_sync(0xffffffffu, myWic, k);
        const float vw = __shfl_sync(0xffffffffu, myWv,  k);
        const int   ib = __shfl_sync(0xffffffffu, myBic, k);
        const float vb = __shfl_sync(0xffffffffu, myBv,  k);

        // 32-bit address math: row offset iw*256 + h0 < 2^25, no 64-bit LEA pairs
        const float* rw = ftw + (iw * 256 + h0);
        const float* rb = ftw + (ib * 256 + h0);
        const float4 w0 = *reinterpret_cast<const float4*>(rw);
        const float4 w1 = *reinterpret_cast<const float4*>(rw + 128);
        const float4 v0 = *reinterpret_cast<const float4*>(rb);
        const float4 v1 = *reinterpret_cast<const float4*>(rb + 128);

        aW0.x += vw*w0.x; aW0.y += vw*w0.y; aW0.z += vw*w0.z; aW0.w += vw*w0.w;
        aW1.x += vw*w1.x; aW1.y += vw*w1.y; aW1.z += vw*w1.z; aW1.w += vw*w1.w;
        aB0.x += vb*v0.x; aB0.y += vb*v0.y; aB0.z += vb*v0.z; aB0.w += vb*v0.w;
        aB1.x += vb*v1.x; aB1.y += vb*v1.y; aB1.z += vb*v1.z; aB1.w += vb*v1.w;
    }

    const float4 bias0 = *reinterpret_cast<const float4*>(ftb + h0);
    const float4 bias1 = *reinterpret_cast<const float4*>(ftb + 128 + h0);

    float4 xw0, xw1, xb0, xb1;
    xw0.x = clip01(aW0.x + bias0.x); xw0.y = clip01(aW0.y + bias0.y);
    xw0.z = clip01(aW0.z + bias0.z); xw0.w = clip01(aW0.w + bias0.w);
    xw1.x = clip01(aW1.x + bias1.x); xw1.y = clip01(aW1.y + bias1.y);
    xw1.z = clip01(aW1.z + bias1.z); xw1.w = clip01(aW1.w + bias1.w);
    xb0.x = clip01(aB0.x + bias0.x); xb0.y = clip01(aB0.y + bias0.y);
    xb0.z = clip01(aB0.z + bias0.z); xb0.w = clip01(aB0.w + bias0.w);
    xb1.x = clip01(aB1.x + bias1.x); xb1.y = clip01(aB1.y + bias1.y);
    xb1.z = clip01(aB1.z + bias1.z); xb1.w = clip01(aB1.w + bias1.w);

    // stm swap via store offset (no per-element selects)
    const int s    = stm[b0 + item];
    const int offW = s * 256;
    const int offB = 256 - offW;
    *reinterpret_cast<float4*>(&sx[item][offW + h0])       = xw0;
    *reinterpret_cast<float4*>(&sx[item][offW + 128 + h0]) = xw1;
    *reinterpret_cast<float4*>(&sx[item][offB + h0])       = xb0;
    *reinterpret_cast<float4*>(&sx[item][offB + 128 + h0]) = xb1;
    __syncthreads();

    // ---- fc1: 512 -> 32, amortized across NB items ----
    #pragma unroll
    for (int rr = 0; rr < 4; rr++) {
        const int r = warp * 4 + rr;
        const float* wr = fc1w + r * 512;
        float p[NB];
        #pragma unroll
        for (int i = 0; i < NB; i++) p[i] = 0.f;
        #pragma unroll
        for (int t = 0; t < 16; t++) {
            const int   j   = lane + t * 32;
            const float wv2 = wr[j];           // coalesced, L1-hot
            #pragma unroll
            for (int i = 0; i < NB; i++)
                p[i] += wv2 * sx[i][j];        // conflict-free smem
        }
        #pragma unroll
        for (int off = 16; off; off >>= 1) {
            #pragma unroll
            for (int i = 0; i < NB; i++)
                p[i] += __shfl_xor_sync(0xffffffffu, p[i], off);
        }
        if (lane == 0) {
            const float bb = fc1b[r];
            #pragma unroll
            for (int i = 0; i < NB; i++)
                sh1[i][r] = clip01(p[i] + bb);
        }
    }
    __syncthreads();

    // ---- fc2 (32->32) + fco (32->1): one warp per item ----
    {
        float sum = 0.f;
        #pragma unroll
        for (int j = 0; j < 32; j++)
            sum += sh1[item][j] * s_fc2[lane][j];
        const float h2 = clip01(sum + fc2b[lane]);
        float o = h2 * fcow[lane];
        #pragma unroll
        for (int off = 16; off; off >>= 1)
            o += __shfl_xor_sync(0xffffffffu, o, off);
        if (lane == 0)
            out[b0 + item] = o + fcob[0];
    }
}

extern "C" void kernel_launch(void* const* d_in, const int* in_sizes, int n_in,
                              void* d_out, int out_size)
{
    const int*   wic  = (const int*)  d_in[0];
    const float* wval = (const float*)d_in[1];
    const int*   bic  = (const int*)  d_in[2];
    const float* bval = (const float*)d_in[3];
    const int*   stm  = (const int*)  d_in[4];
    const float* ftw  = (const float*)d_in[5];
    const float* ftb  = (const float*)d_in[6];
    const float* fc1w = (const float*)d_in[7];
    const float* fc1b = (const float*)d_in[8];
    const float* fc2w = (const float*)d_in[9];
    const float* fc2b = (const float*)d_in[10];
    const float* fcow = (const float*)d_in[11];
    const float* fcob = (const float*)d_in[12];
    float* out = (float*)d_out;

    const int B = in_sizes[4];          // stm is [B,1]
    const int grid = (B + NB - 1) / NB; // B=16384 -> 2048 blocks

    nnue_kernel<<<grid, THREADS>>>(wic, wval, bic, bval, stm,
                                   ftw, ftb, fc1w, fc1b, fc2w, fc2b,
                                   fcow, fcob, out);
}

// round 11
// speedup vs baseline: 1.1828x; 1.1828x over previous
#include <cuda_runtime.h>
#include <cuda_bf16.h>

#define NB 8
#define THREADS 256   // 8 warps; warp w owns batch item b0+w

__device__ __forceinline__ float clip01(float v) { return fminf(fmaxf(v, 0.0f), 1.0f); }

__global__ __launch_bounds__(THREADS, 2)   // 128-reg budget: unroll-4 gather fits WITHOUT spills
void nnue_kernel(const int*   __restrict__ wic,  const float* __restrict__ wval,
                 const int*   __restrict__ bic,  const float* __restrict__ bval,
                 const int*   __restrict__ stm,
                 const float* __restrict__ ftw,  const float* __restrict__ ftb,
                 const float* __restrict__ fc1w, const float* __restrict__ fc1b,
                 const float* __restrict__ fc2w, const float* __restrict__ fc2b,
                 const float* __restrict__ fcow, const float* __restrict__ fcob,
                 float* __restrict__ out)
{
    __shared__ float sx[NB][512];      // concat'd + clipped FT outputs
    __shared__ float sh1[NB][32];      // fc1 outputs
    __shared__ float s_fc2[32][33];    // padded: conflict-free row access

    const int tid  = threadIdx.x;
    const int warp = tid >> 5;
    const int lane = tid & 31;
    const int b0   = blockIdx.x * NB;
    const int item = warp;             // one warp per batch item

    // fc2 weights into padded shared (coalesced 4 KB read)
    for (int i = tid; i < 32 * 32; i += THREADS)
        s_fc2[i >> 5][i & 31] = fc2w[i];

    // ---- per-lane sparse slot (k = lane); broadcast later via shfl ----
    // Unconditional loads (dense [B,K]); padding handled arithmetically:
    // -1 -> row 0, value 0 (row 0 stays L1-hot, ~0 extra L2 traffic).
    const int   g   = (b0 + item) * 32 + lane;
    const int   wi  = wic[g];
    const int   bi  = bic[g];
    const float wv  = wval[g];
    const float bv  = bval[g];
    const int   myWic = wi < 0 ? 0 : wi;
    const int   myBic = bi < 0 ? 0 : bi;
    const float myWv  = wi < 0 ? 0.f : wv;
    const float myBv  = bi < 0 ? 0.f : bv;

    // ---- feature-transformer gather: warp-per-item, 2 float4/thread/row ----
    // thread covers H positions [4L..4L+3] and [128+4L..128+4L+3]
    const int h0 = lane * 4;

    float4 aW0 = make_float4(0.f,0.f,0.f,0.f), aW1 = make_float4(0.f,0.f,0.f,0.f);
    float4 aB0 = make_float4(0.f,0.f,0.f,0.f), aB1 = make_float4(0.f,0.f,0.f,0.f);

    // unroll 4: ~16 LDG.128 destinations alive (64 regs) + 16 acc regs
    // -> ~115 regs total, fits the 2-CTA budget cleanly (round-9 cap of 80 spilled).
    #pragma unroll 4
    for (int k = 0; k < 32; k++) {
        const int   iw = __shfl_sync(0xffffffffu, myWic, k);
        const float vw = __shfl_sync(0xffffffffu, myWv,  k);
        const int   ib = __shfl_sync(0xffffffffu, myBic, k);
        const float vb = __shfl_sync(0xffffffffu, myBv,  k);

        // 32-bit address math: row offset < 2^25, no 64-bit LEA pairs
        const float* rw = ftw + (iw * 256 + h0);
        const float* rb = ftw + (ib * 256 + h0);
        const float4 w0 = *reinterpret_cast<const float4*>(rw);
        const float4 w1 = *reinterpret_cast<const float4*>(rw + 128);
        const float4 v0 = *reinterpret_cast<const float4*>(rb);
        const float4 v1 = *reinterpret_cast<const float4*>(rb + 128);

        aW0.x += vw*w0.x; aW0.y += vw*w0.y; aW0.z += vw*w0.z; aW0.w += vw*w0.w;
        aW1.x += vw*w1.x; aW1.y += vw*w1.y; aW1.z += vw*w1.z; aW1.w += vw*w1.w;
        aB0.x += vb*v0.x; aB0.y += vb*v0.y; aB0.z += vb*v0.z; aB0.w += vb*v0.w;
        aB1.x += vb*v1.x; aB1.y += vb*v1.y; aB1.z += vb*v1.z; aB1.w += vb*v1.w;
    }

    const float4 bias0 = *reinterpret_cast<const float4*>(ftb + h0);
    const float4 bias1 = *reinterpret_cast<const float4*>(ftb + 128 + h0);

    float4 xw0, xw1, xb0, xb1;
    xw0.x = clip01(aW0.x + bias0.x); xw0.y = clip01(aW0.y + bias0.y);
    xw0.z = clip01(aW0.z + bias0.z); xw0.w = clip01(aW0.w + bias0.w);
    xw1.x = clip01(aW1.x + bias1.x); xw1.y = clip01(aW1.y + bias1.y);
    xw1.z = clip01(aW1.z + bias1.z); xw1.w = clip01(aW1.w + bias1.w);
    xb0.x = clip01(aB0.x + bias0.x); xb0.y = clip01(aB0.y + bias0.y);
    xb0.z = clip01(aB0.z + bias0.z); xb0.w = clip01(aB0.w + bias0.w);
    xb1.x = clip01(aB1.x + bias1.x); xb1.y = clip01(aB1.y + bias1.y);
    xb1.z = clip01(aB1.z + bias1.z); xb1.w = clip01(aB1.w + bias1.w);

    // stm swap via store offset (no per-element selects)
    const int s    = stm[b0 + item];
    const int offW = s * 256;
    const int offB = 256 - offW;
    *reinterpret_cast<float4*>(&sx[item][offW + h0])       = xw0;
    *reinterpret_cast<float4*>(&sx[item][offW + 128 + h0]) = xw1;
    *reinterpret_cast<float4*>(&sx[item][offB + h0])       = xb0;
    *reinterpret_cast<float4*>(&sx[item][offB + 128 + h0]) = xb1;
    __syncthreads();

    // ---- fc1: 512 -> 32, amortized across NB items ----
    #pragma unroll
    for (int rr = 0; rr < 4; rr++) {
        const int r = warp * 4 + rr;
        const float* wr = fc1w + r * 512;
        float p[NB];
        #pragma unroll
        for (int i = 0; i < NB; i++) p[i] = 0.f;
        #pragma unroll
        for (int t = 0; t < 16; t++) {
            const int   j   = lane + t * 32;
            const float wv2 = wr[j];           // coalesced, L1-hot
            #pragma unroll
            for (int i = 0; i < NB; i++)
                p[i] += wv2 * sx[i][j];        // conflict-free smem
        }
        #pragma unroll
        for (int off = 16; off; off >>= 1) {
            #pragma unroll
            for (int i = 0; i < NB; i++)
                p[i] += __shfl_xor_sync(0xffffffffu, p[i], off);
        }
        if (lane == 0) {
            const float bb = fc1b[r];
            #pragma unroll
            for (int i = 0; i < NB; i++)
                sh1[i][r] = clip01(p[i] + bb);
        }
    }
    __syncthreads();

    // ---- fc2 (32->32) + fco (32->1): one warp per item ----
    {
        float sum = 0.f;
        #pragma unroll
        for (int j = 0; j < 32; j++)
            sum += sh1[item][j] * s_fc2[lane][j];
        const float h2 = clip01(sum + fc2b[lane]);
        float o = h2 * fcow[lane];
        #pragma unroll
        for (int off = 16; off; off >>= 1)
            o += __shfl_xor_sync(0xffffffffu, o, off);
        if (lane == 0)
            out[b0 + item] = o + fcob[0];
    }
}

extern "C" void kernel_launch(void* const* d_in, const int* in_sizes, int n_in,
                              void* d_out, int out_size)
{
    const int*   wic  = (const int*)  d_in[0];
    const float* wval = (const float*)d_in[1];
    const int*   bic  = (const int*)  d_in[2];
    const float* bval = (const float*)d_in[3];
    const int*   stm  = (const int*)  d_in[4];
    const float* ftw  = (const float*)d_in[5];
    const float* ftb  = (const float*)d_in[6];
    const float* fc1w = (const float*)d_in[7];
    const float* fc1b = (const float*)d_in[8];
    const float* fc2w = (const float*)d_in[9];
    const float* fc2b = (const float*)d_in[10];
    const float* fcow = (const float*)d_in[11];
    const float* fcob = (const float*)d_in[12];
    float* out = (float*)d_out;

    const int B = in_sizes[4];          // stm is [B,1]
    const int grid = (B + NB - 1) / NB; // B=16384 -> 2048 blocks

    nnue_kernel<<<grid, THREADS>>>(wic, wval, bic, bval, stm,
                                   ftw, ftb, fc1w, fc1b, fc2w, fc2b,
                                   fcow, fcob, out);
}

// round 12
// speedup vs baseline: 1.2034x; 1.0174x over previous
#include <cuda_runtime.h>
#include <cuda_fp16.h>

#define NB 8
#define THREADS 256   // 8 warps; warp w owns batch item b0+w

#define N_FTS 40960
#define H     256

// 20 MB fp16 copy of the feature table (scratch: __device__ global, no allocs)
__device__ __half d_ftw_h[N_FTS * H];

__device__ __forceinline__ float clip01(float v) { return fminf(fmaxf(v, 0.0f), 1.0f); }

// ---- pre-pass: ftw f32 -> f16 (runs every launch; ~5-7 us) ----
__global__ __launch_bounds__(256)
void cvt_kernel(const float* __restrict__ src, int n)
{
    const int base = (blockIdx.x * 256 + threadIdx.x) * 4;
    if (base < n) {
        const float4 f = *reinterpret_cast<const float4*>(src + base);
        __half2 h01 = __floats2half2_rn(f.x, f.y);
        __half2 h23 = __floats2half2_rn(f.z, f.w);
        uint2 packed;
        packed.x = *reinterpret_cast<const unsigned*>(&h01);
        packed.y = *reinterpret_cast<const unsigned*>(&h23);
        *reinterpret_cast<uint2*>(&d_ftw_h[base]) = packed;
    }
}

__global__ __launch_bounds__(THREADS, 2)
void nnue_kernel(const int*   __restrict__ wic,  const float* __restrict__ wval,
                 const int*   __restrict__ bic,  const float* __restrict__ bval,
                 const int*   __restrict__ stm,
                 const float* __restrict__ ftb,
                 const float* __restrict__ fc1w, const float* __restrict__ fc1b,
                 const float* __restrict__ fc2w, const float* __restrict__ fc2b,
                 const float* __restrict__ fcow, const float* __restrict__ fcob,
                 float* __restrict__ out)
{
    __shared__ float sx[NB][512];      // concat'd + clipped FT outputs
    __shared__ float sh1[NB][32];      // fc1 outputs
    __shared__ float s_fc2[32][33];    // padded: conflict-free row access

    const int tid  = threadIdx.x;
    const int warp = tid >> 5;
    const int lane = tid & 31;
    const int b0   = blockIdx.x * NB;
    const int item = warp;             // one warp per batch item

    // fc2 weights into padded shared (coalesced 4 KB read)
    for (int i = tid; i < 32 * 32; i += THREADS)
        s_fc2[i >> 5][i & 31] = fc2w[i];

    // ---- per-lane sparse slot (k = lane); broadcast later via shfl ----
    // Unconditional loads; padding arithmetically: -1 -> row 0, value 0.
    const int   g   = (b0 + item) * 32 + lane;
    const int   wi  = wic[g];
    const int   bi  = bic[g];
    const float wv  = wval[g];
    const float bv  = bval[g];
    const int   myWic = wi < 0 ? 0 : wi;
    const int   myBic = bi < 0 ? 0 : bi;
    const float myWv  = wi < 0 ? 0.f : wv;
    const float myBv  = bi < 0 ? 0.f : bv;

    // ---- gather: warp-per-item, fp16 table, 8 H-lanes per thread ----
    // one LDG.128 covers a full 512B row per table (32 lanes x 8 halves)
    const int h0 = lane * 8;
    const __half* tw = d_ftw_h;

    float accW[8], accB[8];
    #pragma unroll
    for (int i = 0; i < 8; i++) { accW[i] = 0.f; accB[i] = 0.f; }

    // 2 independent LDG.128 per iter; unroll 8 -> 16 in flight (64 regs), no spills
    #pragma unroll 8
    for (int k = 0; k < 32; k++) {
        const int   iw = __shfl_sync(0xffffffffu, myWic, k);
        const float vw = __shfl_sync(0xffffffffu, myWv,  k);
        const int   ib = __shfl_sync(0xffffffffu, myBic, k);
        const float vb = __shfl_sync(0xffffffffu, myBv,  k);

        const uint4 wq = *reinterpret_cast<const uint4*>(tw + (iw << 8) + h0);
        const uint4 bq = *reinterpret_cast<const uint4*>(tw + (ib << 8) + h0);

        const float2 wf0 = __half22float2(*reinterpret_cast<const __half2*>(&wq.x));
        const float2 wf1 = __half22float2(*reinterpret_cast<const __half2*>(&wq.y));
        const float2 wf2 = __half22float2(*reinterpret_cast<const __half2*>(&wq.z));
        const float2 wf3 = __half22float2(*reinterpret_cast<const __half2*>(&wq.w));
        accW[0] += vw * wf0.x; accW[1] += vw * wf0.y;
        accW[2] += vw * wf1.x; accW[3] += vw * wf1.y;
        accW[4] += vw * wf2.x; accW[5] += vw * wf2.y;
        accW[6] += vw * wf3.x; accW[7] += vw * wf3.y;

        const float2 bf0 = __half22float2(*reinterpret_cast<const __half2*>(&bq.x));
        const float2 bf1 = __half22float2(*reinterpret_cast<const __half2*>(&bq.y));
        const float2 bf2 = __half22float2(*reinterpret_cast<const __half2*>(&bq.z));
        const float2 bf3 = __half22float2(*reinterpret_cast<const __half2*>(&bq.w));
        accB[0] += vb * bf0.x; accB[1] += vb * bf0.y;
        accB[2] += vb * bf1.x; accB[3] += vb * bf1.y;
        accB[4] += vb * bf2.x; accB[5] += vb * bf2.y;
        accB[6] += vb * bf3.x; accB[7] += vb * bf3.y;
    }

    // bias + clip; stm swap via store offset
    const int s    = stm[b0 + item];
    const int offW = s * 256;
    const int offB = 256 - offW;
    #pragma unroll
    for (int i = 0; i < 8; i++) {
        const float bb = ftb[h0 + i];
        sx[item][offW + h0 + i] = clip01(accW[i] + bb);
        sx[item][offB + h0 + i] = clip01(accB[i] + bb);
    }
    __syncthreads();

    // ---- fc1: 512 -> 32, amortized across NB items ----
    #pragma unroll
    for (int rr = 0; rr < 4; rr++) {
        const int r = warp * 4 + rr;
        const float* wr = fc1w + r * 512;
        float p[NB];
        #pragma unroll
        for (int i = 0; i < NB; i++) p[i] = 0.f;
        #pragma unroll
        for (int t = 0; t < 16; t++) {
            const int   j   = lane + t * 32;
            const float wv2 = wr[j];           // coalesced, L1-hot
            #pragma unroll
            for (int i = 0; i < NB; i++)
                p[i] += wv2 * sx[i][j];        // conflict-free smem
        }
        #pragma unroll
        for (int off = 16; off; off >>= 1) {
            #pragma unroll
            for (int i = 0; i < NB; i++)
                p[i] += __shfl_xor_sync(0xffffffffu, p[i], off);
        }
        if (lane == 0) {
            const float bb = fc1b[r];
            #pragma unroll
            for (int i = 0; i < NB; i++)
                sh1[i][r] = clip01(p[i] + bb);
        }
    }
    __syncthreads();

    // ---- fc2 (32->32) + fco (32->1): one warp per item ----
    {
        float sum = 0.f;
        #pragma unroll
        for (int j = 0; j < 32; j++)
            sum += sh1[item][j] * s_fc2[lane][j];
        const float h2 = clip01(sum + fc2b[lane]);
        float o = h2 * fcow[lane];
        #pragma unroll
        for (int off = 16; off; off >>= 1)
            o += __shfl_xor_sync(0xffffffffu, o, off);
        if (lane == 0)
            out[b0 + item] = o + fcob[0];
    }
}

extern "C" void kernel_launch(void* const* d_in, const int* in_sizes, int n_in,
                              void* d_out, int out_size)
{
    const int*   wic  = (const int*)  d_in[0];
    const float* wval = (const float*)d_in[1];
    const int*   bic  = (const int*)  d_in[2];
    const float* bval = (const float*)d_in[3];
    const int*   stm  = (const int*)  d_in[4];
    const float* ftw  = (const float*)d_in[5];
    const float* ftb  = (const float*)d_in[6];
    const float* fc1w = (const float*)d_in[7];
    const float* fc1b = (const float*)d_in[8];
    const float* fc2w = (const float*)d_in[9];
    const float* fc2b = (const float*)d_in[10];
    const float* fcow = (const float*)d_in[11];
    const float* fcob = (const float*)d_in[12];
    float* out = (float*)d_out;

    // pre-pass: fp32 table -> fp16 scratch (same stream, ordered before nnue)
    const int nT = in_sizes[5];                  // 40960*256
    cvt_kernel<<<(nT / 4 + 255) / 256, 256>>>(ftw, nT);

    const int B = in_sizes[4];          // stm is [B,1]
    const int grid = (B + NB - 1) / NB; // B=16384 -> 2048 blocks

    nnue_kernel<<<grid, THREADS>>>(wic, wval, bic, bval, stm,
                                   ftb, fc1w, fc1b, fc2w, fc2b,
                                   fcow, fcob, out);
}

// round 16
// speedup vs baseline: 1.4126x; 1.1739x over previous
#include <cuda_runtime.h>
#include <cuda_fp16.h>

#define NB 8
#define THREADS 256   // 8 warps; warp w owns batch item b0+w

#define N_FTS 40960
#define H     256

// 20 MB fp16 copy of the feature table (scratch: __device__ global, no allocs)
__device__ __half d_ftw_h[N_FTS * H];

__device__ __forceinline__ float clip01(float v) { return fminf(fmaxf(v, 0.0f), 1.0f); }

// ---- pre-pass: ftw f32 -> f16 (runs every launch; ~2-6 us) ----
__global__ __launch_bounds__(256)
void cvt_kernel(const float* __restrict__ src, int n)
{
    const int base = (blockIdx.x * 256 + threadIdx.x) * 4;
    if (base < n) {
        const float4 f = *reinterpret_cast<const float4*>(src + base);
        __half2 h01 = __floats2half2_rn(f.x, f.y);
        __half2 h23 = __floats2half2_rn(f.z, f.w);
        uint2 packed;
        packed.x = *reinterpret_cast<const unsigned*>(&h01);
        packed.y = *reinterpret_cast<const unsigned*>(&h23);
        *reinterpret_cast<uint2*>(&d_ftw_h[base]) = packed;
    }
}

// No minBlocks cap: let ptxas take ~175 regs for a 32-deep LDG.128 window
// (R8 proved 178 regs / 1 CTA/SM runs clean; spills, not occupancy, are the enemy).
__global__ __launch_bounds__(THREADS)
void nnue_kernel(const int*   __restrict__ wic,  const float* __restrict__ wval,
                 const int*   __restrict__ bic,  const float* __restrict__ bval,
                 const int*   __restrict__ stm,
                 const float* __restrict__ ftb,
                 const float* __restrict__ fc1w, const float* __restrict__ fc1b,
                 const float* __restrict__ fc2w, const float* __restrict__ fc2b,
                 const float* __restrict__ fcow, const float* __restrict__ fcob,
                 float* __restrict__ out)
{
    __shared__ float sx[NB][512];      // concat'd + clipped FT outputs
    __shared__ float sh1[NB][32];      // fc1 outputs
    __shared__ float s_fc2[32][33];    // padded: conflict-free row access

    const int tid  = threadIdx.x;
    const int warp = tid >> 5;
    const int lane = tid & 31;
    const int b0   = blockIdx.x * NB;
    const int item = warp;             // one warp per batch item

    // fc2 weights into padded shared (coalesced 4 KB read)
    for (int i = tid; i < 32 * 32; i += THREADS)
        s_fc2[i >> 5][i & 31] = fc2w[i];

    // ---- per-lane sparse slot (k = lane); broadcast later via shfl ----
    // Unconditional loads; padding arithmetically: -1 -> row 0, value 0.
    const int   g   = (b0 + item) * 32 + lane;
    const int   wi  = wic[g];
    const int   bi  = bic[g];
    const float wv  = wval[g];
    const float bv  = bval[g];
    const int   myWic = wi < 0 ? 0 : wi;
    const int   myBic = bi < 0 ? 0 : bi;
    const float myWv  = wi < 0 ? 0.f : wv;
    const float myBv  = bi < 0 ? 0.f : bv;

    // ---- gather: warp-per-item, fp16 table, 8 H-lanes per thread ----
    // one LDG.128 covers a full 512B row per table (32 lanes x 8 halves)
    const int h0 = lane * 8;
    const __half* tw = d_ftw_h;

    float accW[8], accB[8];
    #pragma unroll
    for (int i = 0; i < 8; i++) { accW[i] = 0.f; accB[i] = 0.f; }

    // unroll 16: 32 LDG.128 in flight (128 dest regs) -> only 2 exposure
    // batches of L2 latency for the whole 64-row gather.
    #pragma unroll 16
    for (int k = 0; k < 32; k++) {
        const int   iw = __shfl_sync(0xffffffffu, myWic, k);
        const float vw = __shfl_sync(0xffffffffu, myWv,  k);
        const int   ib = __shfl_sync(0xffffffffu, myBic, k);
        const float vb = __shfl_sync(0xffffffffu, myBv,  k);

        const uint4 wq = *reinterpret_cast<const uint4*>(tw + (iw << 8) + h0);
        const uint4 bq = *reinterpret_cast<const uint4*>(tw + (ib << 8) + h0);

        const float2 wf0 = __half22float2(*reinterpret_cast<const __half2*>(&wq.x));
        const float2 wf1 = __half22float2(*reinterpret_cast<const __half2*>(&wq.y));
        const float2 wf2 = __half22float2(*reinterpret_cast<const __half2*>(&wq.z));
        const float2 wf3 = __half22float2(*reinterpret_cast<const __half2*>(&wq.w));
        accW[0] += vw * wf0.x; accW[1] += vw * wf0.y;
        accW[2] += vw * wf1.x; accW[3] += vw * wf1.y;
        accW[4] += vw * wf2.x; accW[5] += vw * wf2.y;
        accW[6] += vw * wf3.x; accW[7] += vw * wf3.y;

        const float2 bf0 = __half22float2(*reinterpret_cast<const __half2*>(&bq.x));
        const float2 bf1 = __half22float2(*reinterpret_cast<const __half2*>(&bq.y));
        const float2 bf2 = __half22float2(*reinterpret_cast<const __half2*>(&bq.z));
        const float2 bf3 = __half22float2(*reinterpret_cast<const __half2*>(&bq.w));
        accB[0] += vb * bf0.x; accB[1] += vb * bf0.y;
        accB[2] += vb * bf1.x; accB[3] += vb * bf1.y;
        accB[4] += vb * bf2.x; accB[5] += vb * bf2.y;
        accB[6] += vb * bf3.x; accB[7] += vb * bf3.y;
    }

    // bias + clip; stm swap via store offset
    const int s    = stm[b0 + item];
    const int offW = s * 256;
    const int offB = 256 - offW;
    #pragma unroll
    for (int i = 0; i < 8; i++) {
        const float bb = ftb[h0 + i];
        sx[item][offW + h0 + i] = clip01(accW[i] + bb);
        sx[item][offB + h0 + i] = clip01(accB[i] + bb);
    }
    __syncthreads();

    // ---- fc1: 512 -> 32, amortized across NB items ----
    #pragma unroll
    for (int rr = 0; rr < 4; rr++) {
        const int r = warp * 4 + rr;
        const float* wr = fc1w + r * 512;
        float p[NB];
        #pragma unroll
        for (int i = 0; i < NB; i++) p[i] = 0.f;
        #pragma unroll
        for (int t = 0; t < 16; t++) {
            const int   j   = lane + t * 32;
            const float wv2 = wr[j];           // coalesced, L1-hot
            #pragma unroll
            for (int i = 0; i < NB; i++)
                p[i] += wv2 * sx[i][j];        // conflict-free smem
        }
        #pragma unroll
        for (int off = 16; off; off >>= 1) {
            #pragma unroll
            for (int i = 0; i < NB; i++)
                p[i] += __shfl_xor_sync(0xffffffffu, p[i], off);
        }
        if (lane == 0) {
            const float bb = fc1b[r];
            #pragma unroll
            for (int i = 0; i < NB; i++)
                sh1[i][r] = clip01(p[i] + bb);
        }
    }
    __syncthreads();

    // ---- fc2 (32->32) + fco (32->1): one warp per item ----
    {
        float sum = 0.f;
        #pragma unroll
        for (int j = 0; j < 32; j++)
            sum += sh1[item][j] * s_fc2[lane][j];
        const float h2 = clip01(sum + fc2b[lane]);
        float o = h2 * fcow[lane];
        #pragma unroll
        for (int off = 16; off; off >>= 1)
            o += __shfl_xor_sync(0xffffffffu, o, off);
        if (lane == 0)
            out[b0 + item] = o + fcob[0];
    }
}

extern "C" void kernel_launch(void* const* d_in, const int* in_sizes, int n_in,
                              void* d_out, int out_size)
{
    const int*   wic  = (const int*)  d_in[0];
    const float* wval = (const float*)d_in[1];
    const int*   bic  = (const int*)  d_in[2];
    const float* bval = (const float*)d_in[3];
    const int*   stm  = (const int*)  d_in[4];
    const float* ftw  = (const float*)d_in[5];
    const float* ftb  = (const float*)d_in[6];
    const float* fc1w = (const float*)d_in[7];
    const float* fc1b = (const float*)d_in[8];
    const float* fc2w = (const float*)d_in[9];
    const float* fc2b = (const float*)d_in[10];
    const float* fcow = (const float*)d_in[11];
    const float* fcob = (const float*)d_in[12];
    float* out = (float*)d_out;

    // pre-pass: fp32 table -> fp16 scratch (same stream, ordered before nnue)
    const int nT = in_sizes[5];                  // 40960*256
    cvt_kernel<<<(nT / 4 + 255) / 256, 256>>>(ftw, nT);

    const int B = in_sizes[4];          // stm is [B,1]
    const int grid = (B + NB - 1) / NB; // B=16384 -> 2048 blocks

    nnue_kernel<<<grid, THREADS>>>(wic, wval, bic, bval, stm,
                                   ftb, fc1w, fc1b, fc2w, fc2b,
                                   fcow, fcob, out);
}